// round 11
// baseline (speedup 1.0000x reference)
#include <cuda_runtime.h>
#include <stdint.h>

#define NALGOS 64
#define NTASKS 1024
#define LXN    512
#define FULLMASK 0xffffffffu

// Scratch (no allocations allowed).
// g_G[s*512 + t] = TM[lx[s]][lx[t]]
__device__ float g_G[LXN * LXN];
__device__ float g_u[NALGOS * LXN];

// 2*sigmoid(z) - 1 == tanh(z/2): single MUFU.TANH, abs err ~2^-11.
__device__ __forceinline__ float tanh_fast(float x) {
    float y;
    asm("tanh.approx.f32 %0, %1;" : "=f"(y) : "f"(x));
    return y;
}
__device__ __forceinline__ void stcs_f32(float* p, float v) {
    asm volatile("st.global.cs.f32 [%0], %1;" :: "l"(p), "f"(v) : "memory");
}

// ---------------------------------------------------------------------------
// Kernel 0: G[s][t] = TM[lx[s]][lx[t]]
// ---------------------------------------------------------------------------
__global__ void build_G(const int* __restrict__ lx, const float* __restrict__ TM) {
    int s = blockIdx.x;
    int t = threadIdx.x;
    int row = __ldg(lx + s);
    int col = __ldg(lx + t);
    g_G[s * LXN + t] = __ldg(TM + row * NTASKS + col);
}

// ---------------------------------------------------------------------------
// Phase 1 (standalone, R9-exact): blocked-scan chain, one 8-warp block per
// algo. Chain warp: branch-free serial path. Bulk warps maintain the full
// 512-col state one chunk behind. u published once at the end.
// NOTE: this kernel is launched TWICE this round. The second launch recomputes
// identical g_u from identical inputs (deterministic, graph-safe). The wall-
// clock delta vs the single-launch round isolates phase1's true duration,
// which has never been directly measurable (ncu keeps profiling build_G).
// ---------------------------------------------------------------------------
__global__ void __launch_bounds__(256, 1) phase1(
    const int* __restrict__ lx, const float* __restrict__ diff,
    const float* __restrict__ eff_, const float* __restrict__ mem_,
    const float* __restrict__ boost_) {

    __shared__ float u_sh[LXN];
    __shared__ float c2_sh[LXN];
    __shared__ float Bnext[2][32];

    int a   = blockIdx.x;
    int tid = threadIdx.x;
    int w = tid >> 5, l = tid & 31;

    float mem = __ldg(mem_ + a), eff = __ldg(eff_ + a), boost = __ldg(boost_ + a);
    float m2 = mem * mem, m4 = m2 * m2, m8 = m4 * m4, m16 = m8 * m8;
    float M32 = m16 * m16;

    for (int t = tid; t < LXN; t += 256)
        c2_sh[t] = 0.5f / __ldg(diff + __ldg(lx + t));
    __syncthreads();

    if (w == 0) {
        // ---- chain warp ----
        float racc = 0.0f, racc2 = 0.0f;
        float c2l = c2_sh[l];
        float my_u = 0.0f;

#pragma unroll 1
        for (int c = 0; c < 16; ++c) {
            int t0 = c * 32;
            const float* gArow = g_G + t0 + l;
            const float* gBrow = g_G + t0 + 32 + l;
            bool hasB = (c < 15);

            float gAe[8], gAb[8], gBe[8], gBb[8];
#pragma unroll
            for (int q = 0; q < 8; ++q) {
                float ga = __ldg(gArow + (t0 + q) * LXN);
                float gb = hasB ? __ldg(gBrow + (t0 + q) * LXN) : 0.0f;
                gAe[q] = ga * eff;  gAb[q] = ga * boost;
                gBe[q] = gb * eff;  gBb[q] = gb * boost;
            }
#pragma unroll
            for (int k = 0; k < 32; ++k) {
                int q = k & 7;
                float th = tanh_fast(racc * c2l);          // all lanes compute
                float thb = __shfl_sync(FULLMASK, th, k);  // owner's value
                my_u = (l == k) ? fmaf(th, boost, eff) : my_u;
                racc  = fmaf(thb, gAb[q], fmaf(racc,  mem, gAe[q]));
                racc2 = fmaf(thb, gBb[q], fmaf(racc2, mem, gBe[q]));
                if (k + 8 < 32) {
                    float ga = __ldg(gArow + (t0 + k + 8) * LXN);
                    float gb = hasB ? __ldg(gBrow + (t0 + k + 8) * LXN) : 0.0f;
                    gAe[q] = ga * eff;  gAb[q] = ga * boost;
                    gBe[q] = gb * eff;  gBb[q] = gb * boost;
                }
            }
            u_sh[t0 + l] = my_u;
            __syncthreads();
            if (c < 15) {
                racc  = fmaf(Bnext[(c + 1) & 1][l], M32, racc2);
                racc2 = 0.0f;
                c2l   = c2_sh[t0 + 32 + l];
            }
        }
    } else {
        // ---- bulk warps 1..7 (one chunk behind) ----
        int base0 = (w - 1) * 32 + l;
        bool has3 = (base0 + 448 < LXN);
        float R0 = 0.0f, R1 = 0.0f, R2v = 0.0f;

#pragma unroll 1
        for (int c = 0; c < 16; ++c) {
            if (c >= 1) {
                int s0 = (c - 1) * 32;
                const float* g0 = g_G + base0;
#pragma unroll 8
                for (int k = 0; k < 32; ++k) {
                    float u = u_sh[s0 + k];
                    const float* gr = g0 + (s0 + k) * LXN;
                    R0 = fmaf(R0, mem, __ldg(gr) * u);
                    R1 = fmaf(R1, mem, __ldg(gr + 224) * u);
                    if (has3) R2v = fmaf(R2v, mem, __ldg(gr + 448) * u);
                }
            }
            int b = c + 1;
            if (b <= 15 && (w - 1) == (b % 7)) {
                int i = b / 7;
                float Rv = (i == 0) ? R0 : (i == 1) ? R1 : R2v;
                Bnext[b & 1][l] = Rv;
            }
            __syncthreads();
        }
    }

    // final publish, all 8 warps, coalesced
    __syncthreads();
    for (int t = tid; t < LXN; t += 256)
        g_u[a * LXN + t] = u_sh[t];
}

// ---------------------------------------------------------------------------
// Phase 2 (standalone, R9-exact): 65536 independent column scans.
// ---------------------------------------------------------------------------
__global__ void __launch_bounds__(256) phase2(
    const int* __restrict__ lx, const float* __restrict__ TM,
    const float* __restrict__ diff, const float* __restrict__ mem_,
    float* __restrict__ out) {

    __shared__ float u_sh[LXN];
    __shared__ int   off_sh[LXN];
    __shared__ float tbuf_all[8 * 32 * 36];

    int a   = blockIdx.y;
    int jb  = blockIdx.x;
    int tid = threadIdx.x;
    int w = tid >> 5, l = tid & 31;
    int j = jb * 256 + tid;
    float* tbuf = tbuf_all + w * (32 * 36);

    for (int i = tid; i < LXN; i += 256) {
        u_sh[i]   = g_u[a * LXN + i];
        off_sh[i] = __ldg(lx + i) << 10;
    }
    __syncthreads();

    float mem = __ldg(mem_ + a);
    float c2  = 0.5f / __ldg(diff + j);
    float r   = 0.0f;

    unsigned obase = (unsigned)(a * NTASKS + j) * 513u;
    stcs_f32(out + obase, 0.0f);                       // step-0 zeros
    unsigned tbase = (unsigned)(a * NTASKS + jb * 256 + w * 32) * 513u
                     + 1u + (unsigned)l;
    const float* TMj = TM + j;

#pragma unroll 1
    for (int c = 0; c < 16; ++c) {
        float v[32];
#pragma unroll
        for (int k = 0; k < 32; ++k)
            v[k] = __ldg(TMj + off_sh[c * 32 + k]);
#pragma unroll
        for (int g = 0; g < 8; ++g) {
            float4 s4;
            r = fmaf(r, mem, v[4 * g + 0] * u_sh[c * 32 + 4 * g + 0]);
            s4.x = tanh_fast(r * c2);
            r = fmaf(r, mem, v[4 * g + 1] * u_sh[c * 32 + 4 * g + 1]);
            s4.y = tanh_fast(r * c2);
            r = fmaf(r, mem, v[4 * g + 2] * u_sh[c * 32 + 4 * g + 2]);
            s4.z = tanh_fast(r * c2);
            r = fmaf(r, mem, v[4 * g + 3] * u_sh[c * 32 + 4 * g + 3]);
            s4.w = tanh_fast(r * c2);
            *(float4*)(tbuf + l * 36 + g * 4) = s4;
        }
        __syncwarp();
        unsigned ob = tbase + (unsigned)(c * 32);
#pragma unroll 8
        for (int row = 0; row < 32; ++row)
            stcs_f32(out + ob + (unsigned)row * 513u, tbuf[row * 36 + l]);
        __syncwarp();
    }
}

// ---------------------------------------------------------------------------
extern "C" void kernel_launch(void* const* d_in, const int* in_sizes, int n_in,
                              void* d_out, int out_size) {
    const int*   lx    = (const int*)  d_in[0];
    const float* TM    = (const float*)d_in[1];
    const float* diff  = (const float*)d_in[2];
    const float* eff   = (const float*)d_in[3];
    const float* mem   = (const float*)d_in[4];
    const float* boost = (const float*)d_in[5];
    float* out = (float*)d_out;

    build_G<<<LXN, LXN>>>(lx, TM);
    phase1<<<NALGOS, 256>>>(lx, diff, eff, mem, boost);
    // Duplicate phase1: deterministic identical recompute of g_u.
    // Measurement: total_dur - 84.7us (R9 single-p1 baseline) = phase1 cost.
    // Also shifts ncu's skip-5 window onto a phase1 instance.
    phase1<<<NALGOS, 256>>>(lx, diff, eff, mem, boost);
    phase2<<<dim3(4, NALGOS), 256>>>(lx, TM, diff, mem, out);
}

// round 12
// speedup vs baseline: 1.2256x; 1.2256x over previous
#include <cuda_runtime.h>
#include <stdint.h>

#define NALGOS 64
#define NTASKS 1024
#define LXN    512
#define FULLMASK 0xffffffffu

// Scratch (no allocations allowed).
// g_G[s*512 + t] = TM[lx[s]][lx[t]]
__device__ float g_G[LXN * LXN];
__device__ float g_u[NALGOS * LXN];

// 2*sigmoid(z) - 1 == tanh(z/2): single MUFU.TANH, abs err ~2^-11.
__device__ __forceinline__ float tanh_fast(float x) {
    float y;
    asm("tanh.approx.f32 %0, %1;" : "=f"(y) : "f"(x));
    return y;
}
__device__ __forceinline__ void stcs_f32(float* p, float v) {
    asm volatile("st.global.cs.f32 [%0], %1;" :: "l"(p), "f"(v) : "memory");
}

// ---------------------------------------------------------------------------
// Kernel 0: G[s][t] = TM[lx[s]][lx[t]]
// ---------------------------------------------------------------------------
__global__ void build_G(const int* __restrict__ lx, const float* __restrict__ TM) {
    int s = blockIdx.x;
    int t = threadIdx.x;
    int row = __ldg(lx + s);
    int col = __ldg(lx + t);
    g_G[s * LXN + t] = __ldg(TM + row * NTASKS + col);
}

// ---------------------------------------------------------------------------
// Phase 1 (R9-exact, measured 22.5us): blocked-scan chain, 8-warp block/algo.
// ---------------------------------------------------------------------------
__global__ void __launch_bounds__(256, 1) phase1(
    const int* __restrict__ lx, const float* __restrict__ diff,
    const float* __restrict__ eff_, const float* __restrict__ mem_,
    const float* __restrict__ boost_) {

    __shared__ float u_sh[LXN];
    __shared__ float c2_sh[LXN];
    __shared__ float Bnext[2][32];

    int a   = blockIdx.x;
    int tid = threadIdx.x;
    int w = tid >> 5, l = tid & 31;

    float mem = __ldg(mem_ + a), eff = __ldg(eff_ + a), boost = __ldg(boost_ + a);
    float m2 = mem * mem, m4 = m2 * m2, m8 = m4 * m4, m16 = m8 * m8;
    float M32 = m16 * m16;

    for (int t = tid; t < LXN; t += 256)
        c2_sh[t] = 0.5f / __ldg(diff + __ldg(lx + t));
    __syncthreads();

    if (w == 0) {
        float racc = 0.0f, racc2 = 0.0f;
        float c2l = c2_sh[l];
        float my_u = 0.0f;

#pragma unroll 1
        for (int c = 0; c < 16; ++c) {
            int t0 = c * 32;
            const float* gArow = g_G + t0 + l;
            const float* gBrow = g_G + t0 + 32 + l;
            bool hasB = (c < 15);

            float gAe[8], gAb[8], gBe[8], gBb[8];
#pragma unroll
            for (int q = 0; q < 8; ++q) {
                float ga = __ldg(gArow + (t0 + q) * LXN);
                float gb = hasB ? __ldg(gBrow + (t0 + q) * LXN) : 0.0f;
                gAe[q] = ga * eff;  gAb[q] = ga * boost;
                gBe[q] = gb * eff;  gBb[q] = gb * boost;
            }
#pragma unroll
            for (int k = 0; k < 32; ++k) {
                int q = k & 7;
                float th = tanh_fast(racc * c2l);
                float thb = __shfl_sync(FULLMASK, th, k);
                my_u = (l == k) ? fmaf(th, boost, eff) : my_u;
                racc  = fmaf(thb, gAb[q], fmaf(racc,  mem, gAe[q]));
                racc2 = fmaf(thb, gBb[q], fmaf(racc2, mem, gBe[q]));
                if (k + 8 < 32) {
                    float ga = __ldg(gArow + (t0 + k + 8) * LXN);
                    float gb = hasB ? __ldg(gBrow + (t0 + k + 8) * LXN) : 0.0f;
                    gAe[q] = ga * eff;  gAb[q] = ga * boost;
                    gBe[q] = gb * eff;  gBb[q] = gb * boost;
                }
            }
            u_sh[t0 + l] = my_u;
            __syncthreads();
            if (c < 15) {
                racc  = fmaf(Bnext[(c + 1) & 1][l], M32, racc2);
                racc2 = 0.0f;
                c2l   = c2_sh[t0 + 32 + l];
            }
        }
    } else {
        int base0 = (w - 1) * 32 + l;
        bool has3 = (base0 + 448 < LXN);
        float R0 = 0.0f, R1 = 0.0f, R2v = 0.0f;

#pragma unroll 1
        for (int c = 0; c < 16; ++c) {
            if (c >= 1) {
                int s0 = (c - 1) * 32;
                const float* g0 = g_G + base0;
#pragma unroll 8
                for (int k = 0; k < 32; ++k) {
                    float u = u_sh[s0 + k];
                    const float* gr = g0 + (s0 + k) * LXN;
                    R0 = fmaf(R0, mem, __ldg(gr) * u);
                    R1 = fmaf(R1, mem, __ldg(gr + 224) * u);
                    if (has3) R2v = fmaf(R2v, mem, __ldg(gr + 448) * u);
                }
            }
            int b = c + 1;
            if (b <= 15 && (w - 1) == (b % 7)) {
                int i = b / 7;
                float Rv = (i == 0) ? R0 : (i == 1) ? R1 : R2v;
                Bnext[b & 1][l] = Rv;
            }
            __syncthreads();
        }
    }

    __syncthreads();
    for (int t = tid; t < LXN; t += 256)
        g_u[a * LXN + t] = u_sh[t];
}

// ---------------------------------------------------------------------------
// Phase 2 v2: 4-way blocked scan over t. Block = 256 threads = 4 step-groups
// x 64 columns; grid = 16 j-tiles x 64 algos = 1024 blocks (262144 threads,
// ~40 warps/SM vs 13.8 before — the occ=21% latency wall from ncu R11).
//   Pass 1: groups 0..2 raw-scan their 128 steps from r=0, publish end-state.
//   Prefix: S_g = Horner(E_0..E_{g-1}, mem^128) — mem^128 ~ 0, well-conditioned.
//   Pass 2: all groups scan from S_g with tanh + transpose + streaming stores.
// ---------------------------------------------------------------------------
__global__ void __launch_bounds__(256) phase2(
    const int* __restrict__ lx, const float* __restrict__ TM,
    const float* __restrict__ diff, const float* __restrict__ mem_,
    float* __restrict__ out) {

    __shared__ float u_sh[LXN];
    __shared__ int   off_sh[LXN];
    __shared__ float E_sh[3 * 64];
    __shared__ float tbuf_all[8 * 32 * 36];

    int a   = blockIdx.y;
    int jb  = blockIdx.x;                 // 16 tiles of 64 columns
    int tid = threadIdx.x;
    int g   = tid >> 6;                   // step-group 0..3 (warp-uniform)
    int jj  = tid & 63;
    int j   = jb * 64 + jj;
    int w = tid >> 5, l = tid & 31;
    float* tbuf = tbuf_all + w * (32 * 36);

    for (int i = tid; i < LXN; i += 256) {
        u_sh[i]   = g_u[a * LXN + i];
        off_sh[i] = __ldg(lx + i) << 10;
    }
    __syncthreads();

    float mem = __ldg(mem_ + a);
    float c2  = 0.5f / __ldg(diff + j);
    const float* TMj = TM + j;

    // ---- pass 1: raw partial scans (groups 0..2; group 3's E is unused) ----
    if (g < 3) {
        float r = 0.0f;
        int sg = g * 128;
#pragma unroll 1
        for (int c = 0; c < 4; ++c) {
            int s0 = sg + c * 32;
            float v[32];
#pragma unroll
            for (int k = 0; k < 32; ++k)
                v[k] = __ldg(TMj + off_sh[s0 + k]);
#pragma unroll
            for (int k = 0; k < 32; ++k)
                r = fmaf(r, mem, v[k] * u_sh[s0 + k]);
        }
        E_sh[g * 64 + jj] = r;
    }

    float m128 = mem;
#pragma unroll
    for (int q = 0; q < 7; ++q) m128 *= m128;
    __syncthreads();

    // ---- prefix combine: S_g (g warp-uniform -> no divergence) ----
    float r = 0.0f;
    for (int h = 0; h < g; ++h)
        r = fmaf(r, m128, E_sh[h * 64 + jj]);

    // ---- pass 2: corrected scan + tanh + transpose + store ----
    unsigned obase = (unsigned)(a * NTASKS + j) * 513u;
    if (g == 0) stcs_f32(out + obase, 0.0f);          // step-0 zeros
    unsigned tbase = (unsigned)(a * NTASKS + jb * 64 + (w & 1) * 32) * 513u
                     + 1u + (unsigned)l;

#pragma unroll 1
    for (int c = 0; c < 4; ++c) {
        int s0 = g * 128 + c * 32;
        float v[32];
#pragma unroll
        for (int k = 0; k < 32; ++k)
            v[k] = __ldg(TMj + off_sh[s0 + k]);
#pragma unroll
        for (int q = 0; q < 8; ++q) {
            float4 s4;
            r = fmaf(r, mem, v[4 * q + 0] * u_sh[s0 + 4 * q + 0]);
            s4.x = tanh_fast(r * c2);
            r = fmaf(r, mem, v[4 * q + 1] * u_sh[s0 + 4 * q + 1]);
            s4.y = tanh_fast(r * c2);
            r = fmaf(r, mem, v[4 * q + 2] * u_sh[s0 + 4 * q + 2]);
            s4.z = tanh_fast(r * c2);
            r = fmaf(r, mem, v[4 * q + 3] * u_sh[s0 + 4 * q + 3]);
            s4.w = tanh_fast(r * c2);
            *(float4*)(tbuf + l * 36 + q * 4) = s4;
        }
        __syncwarp();
        unsigned ob = tbase + (unsigned)s0;
#pragma unroll 8
        for (int row = 0; row < 32; ++row)
            stcs_f32(out + ob + (unsigned)row * 513u, tbuf[row * 36 + l]);
        __syncwarp();
    }
}

// ---------------------------------------------------------------------------
extern "C" void kernel_launch(void* const* d_in, const int* in_sizes, int n_in,
                              void* d_out, int out_size) {
    const int*   lx    = (const int*)  d_in[0];
    const float* TM    = (const float*)d_in[1];
    const float* diff  = (const float*)d_in[2];
    const float* eff   = (const float*)d_in[3];
    const float* mem   = (const float*)d_in[4];
    const float* boost = (const float*)d_in[5];
    float* out = (float*)d_out;

    build_G<<<LXN, LXN>>>(lx, TM);
    phase1<<<NALGOS, 256>>>(lx, diff, eff, mem, boost);
    phase2<<<dim3(16, NALGOS), 256>>>(lx, TM, diff, mem, out);
}